// round 11
// baseline (speedup 1.0000x reference)
#include <cuda_runtime.h>

#define N_NODES 2048
#define NGR 512
#define NGRAPH 4
#define NEDGE 32768
#define DIM 128
#define HEADS 4
#define GRID_PTS 500
#define NQ 20
#define NRG 12
#define DEGCAP 64
#define NBLK 148
#define NTHR 512
#define ABLK 48          // GAT team blocks
#define BBLK 100         // KDE team blocks

typedef unsigned long long ull;

__device__ float g_xh[N_NODES*DIM];
__device__ float g_als[N_NODES*HEADS];
__device__ float g_ald[N_NODES*HEADS];
__device__ float g_cur1[N_NODES*DIM];
__device__ float g_xT [DIM*N_NODES];
__device__ float g_c1T[DIM*N_NODES];
__device__ float g_c2T[DIM*N_NODES];
__device__ int   g_cursor[N_NODES];      // zero-init; re-zeroed in epilogue
__device__ int   g_adjB[N_NODES*DEGCAP];
__device__ float g_pool[NRG*DIM];
__device__ float g_kf[NRG*DIM*NQ];
__device__ float g_acc[NGRAPH*32];       // zero-init; reset by last proj block
__device__ int   g_done;
__device__ unsigned g_cnt[3];            // 0: full grid, 1: team A, 2: team B
__device__ volatile unsigned g_gen[3];

__device__ __forceinline__ float ex2(float x){
    float y; asm("ex2.approx.ftz.f32 %0, %1;" : "=f"(y) : "f"(x)); return y;
}
__device__ __forceinline__ float rcpf(float x){
    float y; asm("rcp.approx.ftz.f32 %0, %1;" : "=f"(y) : "f"(x)); return y;
}
__device__ __forceinline__ ull pk2(float lo, float hi){
    ull o; asm("mov.b64 %0, {%1, %2};" : "=l"(o) : "f"(lo), "f"(hi)); return o;
}
__device__ __forceinline__ void up2(float& lo, float& hi, ull v){
    asm("mov.b64 {%0, %1}, %2;" : "=f"(lo), "=f"(hi) : "l"(v));
}
__device__ __forceinline__ ull mul2(ull a, ull b){
    ull o; asm("mul.rn.f32x2 %0, %1, %2;" : "=l"(o) : "l"(a), "l"(b)); return o;
}
__device__ __forceinline__ ull add2(ull a, ull b){
    ull o; asm("add.rn.f32x2 %0, %1, %2;" : "=l"(o) : "l"(a), "l"(b)); return o;
}

// generation barrier over `count` blocks using slot `id`
__device__ __forceinline__ void sync_n(int id, unsigned count){
    __syncthreads();
    if (threadIdx.x == 0){
        __threadfence();
        unsigned gen = g_gen[id];
        if (atomicAdd(&g_cnt[id], 1u) == count-1u){
            atomicExch(&g_cnt[id], 0u);
            __threadfence();
            g_gen[id] = gen + 1u;
        } else {
            while (g_gen[id] == gen) __nanosleep(32);
        }
        __threadfence();
    }
    __syncthreads();
}

#define GROUP_BAR(gid) asm volatile("bar.sync %0, %1;" :: "r"((gid)+4), "r"(128) : "memory")
#define PAIR_BAR(pid)  asm volatile("bar.sync %0, %1;" :: "r"((pid)+8), "r"(64)  : "memory")

// ---------------- lin (Team A): 8-node tiles, 2 sweep iterations ----------------
__device__ void lin_phase(const float* __restrict__ cur,
                          const float* __restrict__ W,
                          const float* __restrict__ as_,
                          const float* __restrict__ ad_,
                          int b, int tid, char* smem){
    int g = tid>>7, gt = tid&127;
    float (*srow)[128] = (float(*)[128])(smem + g*4096);
    for (int iter=0; iter<2; iter++){
        int tI = iter*(4*ABLK) + g*ABLK + b;
        bool act = (tI < N_NODES/8);
        int n0 = tI*8;
        if (act){
            #pragma unroll
            for (int i=0;i<8;i++){
                int idx = gt + i*128;
                srow[idx>>7][idx&127] = cur[(size_t)n0*DIM + idx];
            }
        }
        GROUP_BAR(g);
        if (act){
            float acc[8] = {0,0,0,0,0,0,0,0};
            #pragma unroll 4
            for (int k4=0;k4<32;k4++){
                float w0 = W[(k4*4+0)*DIM + gt];
                float w1 = W[(k4*4+1)*DIM + gt];
                float w2 = W[(k4*4+2)*DIM + gt];
                float w3 = W[(k4*4+3)*DIM + gt];
                #pragma unroll
                for (int j=0;j<8;j++){
                    float4 sv = *(const float4*)&srow[j][k4*4];
                    acc[j] = fmaf(sv.x, w0, acc[j]);
                    acc[j] = fmaf(sv.y, w1, acc[j]);
                    acc[j] = fmaf(sv.z, w2, acc[j]);
                    acc[j] = fmaf(sv.w, w3, acc[j]);
                }
            }
            int hw = gt>>5;
            float a_s = as_[gt], a_d = ad_[gt];
            #pragma unroll
            for (int j=0;j<8;j++){
                g_xh[(size_t)(n0+j)*DIM + gt] = acc[j];
                float ps = acc[j]*a_s, pd = acc[j]*a_d;
                #pragma unroll
                for (int o=16;o;o>>=1){
                    ps += __shfl_xor_sync(0xffffffffu, ps, o);
                    pd += __shfl_xor_sync(0xffffffffu, pd, o);
                }
                if ((gt&31)==0){
                    g_als[(n0+j)*HEADS + hw] = ps;
                    g_ald[(n0+j)*HEADS + hw] = pd;
                }
            }
        }
        GROUP_BAR(g);
    }
}

// ---------------- att (Team A): warp-per-node, 3 sweep iterations ----------------
__device__ void att_phase(const float* __restrict__ bias, int layer,
                          int b, int tid, char* smem){
    int w = tid>>5, lane = tid&31;
    float* outT = layer ? g_c2T : g_c1T;
    char* base = smem + w*1376;
    int*   sadj = (int*)base;            // 68 ints
    float* sal  = (float*)(base + 272);  // [4][68] floats
    float4 bi = *(const float4*)&bias[lane*4];
    for (int iter=0; iter<3; iter++){
        int n = iter*(16*ABLK) + w*ABLK + b;
        if (n >= N_NODES) break;
        int deg = g_cursor[n]; if (deg > DEGCAP) deg = DEGCAP;
        int cnt = deg + 1;
        for (int i=lane; i<cnt; i+=32)
            sadj[i] = (i < deg) ? g_adjB[n*DEGCAP + i] : n;
        __syncwarp();
        int h = lane & 3, sub = lane >> 2;
        float aldn = g_ald[n*HEADS + h];
        int nch = (cnt + 7) >> 3;
        float mx = -1e30f;
        for (int c=0;c<nch;c++){
            int i = c*8 + sub;
            if (i < cnt){
                float z = g_als[sadj[i]*HEADS + h] + aldn;
                z = (z>0.f) ? z : 0.2f*z;
                sal[h*68 + i] = z;
                mx = fmaxf(mx, z);
            }
        }
        mx = fmaxf(mx, __shfl_xor_sync(0xffffffffu, mx, 4));
        mx = fmaxf(mx, __shfl_xor_sync(0xffffffffu, mx, 8));
        mx = fmaxf(mx, __shfl_xor_sync(0xffffffffu, mx, 16));
        float sum = 0.f;
        for (int c=0;c<nch;c++){
            int i = c*8 + sub;
            if (i < cnt){
                float e = __expf(sal[h*68+i] - mx);
                sal[h*68+i] = e;
                sum += e;
            }
        }
        sum += __shfl_xor_sync(0xffffffffu, sum, 4);
        sum += __shfl_xor_sync(0xffffffffu, sum, 8);
        sum += __shfl_xor_sync(0xffffffffu, sum, 16);
        float inv = 1.f/(sum + 1e-16f);
        float invA = __shfl_sync(0xffffffffu, inv, lane>>3);
        __syncwarp();
        const float* salh = sal + (lane>>3)*68;
        float ax=0.f, ay=0.f, az=0.f, aw=0.f;
        int i=0;
        for (; i+4<=cnt; i+=4){
            float a0=salh[i], a1=salh[i+1], a2=salh[i+2], a3=salh[i+3];
            float4 x0 = *(const float4*)&g_xh[(size_t)sadj[i  ]*DIM + lane*4];
            float4 x1 = *(const float4*)&g_xh[(size_t)sadj[i+1]*DIM + lane*4];
            float4 x2 = *(const float4*)&g_xh[(size_t)sadj[i+2]*DIM + lane*4];
            float4 x3 = *(const float4*)&g_xh[(size_t)sadj[i+3]*DIM + lane*4];
            ax=fmaf(a0,x0.x,ax); ay=fmaf(a0,x0.y,ay); az=fmaf(a0,x0.z,az); aw=fmaf(a0,x0.w,aw);
            ax=fmaf(a1,x1.x,ax); ay=fmaf(a1,x1.y,ay); az=fmaf(a1,x1.z,az); aw=fmaf(a1,x1.w,aw);
            ax=fmaf(a2,x2.x,ax); ay=fmaf(a2,x2.y,ay); az=fmaf(a2,x2.z,az); aw=fmaf(a2,x2.w,aw);
            ax=fmaf(a3,x3.x,ax); ay=fmaf(a3,x3.y,ay); az=fmaf(a3,x3.z,az); aw=fmaf(a3,x3.w,aw);
        }
        for (; i<cnt; i++){
            float a0 = salh[i];
            float4 x0 = *(const float4*)&g_xh[(size_t)sadj[i]*DIM + lane*4];
            ax=fmaf(a0,x0.x,ax); ay=fmaf(a0,x0.y,ay); az=fmaf(a0,x0.z,az); aw=fmaf(a0,x0.w,aw);
        }
        ax = fmaf(ax, invA, bi.x); ay = fmaf(ay, invA, bi.y);
        az = fmaf(az, invA, bi.z); aw = fmaf(aw, invA, bi.w);
        if (layer==0){
            ax=fmaxf(ax,0.f); ay=fmaxf(ay,0.f); az=fmaxf(az,0.f); aw=fmaxf(aw,0.f);
            *(float4*)&g_cur1[(size_t)n*DIM + lane*4] = make_float4(ax,ay,az,aw);
        }
        size_t cb = (size_t)(lane*4)*N_NODES + n;
        outT[cb]             = ax;
        outT[cb +   N_NODES] = ay;
        outT[cb + 2*N_NODES] = az;
        outT[cb + 3*N_NODES] = aw;
        __syncwarp();
    }
}

// ---------------- densq: 2 warps per (rg,d) unit; each warp takes 256 nodes ----------------
__device__ void densq_unit2(int rg, int d, const float* __restrict__ pw,
                            char* pmem, float* sred8, int half, int lane, int pid){
    int ro = rg >> 2, g = rg & 3;
    const float* baseT = (ro==0) ? g_xT : (ro==1) ? g_c1T : g_c2T;
    float2* sab = (float2*)pmem;                 // 512 float2 = 4KB per pair
    const float* row = baseT + (size_t)d*N_NODES + g*NGR + half*256;

    float v[8];
    float mn=1e30f, mx=-1e30f, s1=0.f, s2=0.f;
    #pragma unroll
    for (int i=0;i<8;i++){
        float xv = row[i*32 + lane];
        v[i] = xv;
        mn = fminf(mn,xv); mx = fmaxf(mx,xv);
        s1 += xv; s2 = fmaf(xv,xv,s2);
    }
    #pragma unroll
    for (int o=16;o;o>>=1){
        mn = fminf(mn, __shfl_xor_sync(0xffffffffu,mn,o));
        mx = fmaxf(mx, __shfl_xor_sync(0xffffffffu,mx,o));
        s1 += __shfl_xor_sync(0xffffffffu,s1,o);
        s2 += __shfl_xor_sync(0xffffffffu,s2,o);
    }
    if (lane==0){
        sred8[half*4+0]=mn; sred8[half*4+1]=mx;
        sred8[half*4+2]=s1; sred8[half*4+3]=s2;
    }
    PAIR_BAR(pid);
    mn = fminf(sred8[0], sred8[4]);
    mx = fmaxf(sred8[1], sred8[5]);
    s1 = sred8[2] + sred8[6];
    s2 = sred8[3] + sred8[7];

    float mean = s1*(1.f/512.f);
    float var  = fmaxf(s2*(1.f/512.f) - mean*mean, 0.f);
    float stdv = sqrtf(var) + 3.3333333e-9f;
    float h    = 0.30440506f*stdv;                   // 1.06*512^-0.2
    float c2   = -0.72134752f/(h*h);                 // -0.5*log2(e)/h^2
    float mnA = mn - 1e-6f, mxA = mx + 1e-6f;
    float step = (mxA - mnA)*(1.f/499.f);
    float mid  = 0.5f*(mnA + mxA);
    if (lane==0 && half==0) g_pool[rg*DIM + d] = pw[0]*mean + pw[1]*mx;

    // fill own half of sab
    #pragma unroll
    for (int i=0;i<8;i++){
        float xc = v[i] - mid;
        sab[half*256 + i*32 + lane] = make_float2(c2*xc*xc, -2.f*c2*xc);
    }
    __syncwarp();

    float mnc = mnA - mid;
    float g0  = fmaf((float)(lane*16), step, mnc);
    float q0  = c2*g0*g0;
    float K1  = 2.f*c2*step, K2 = c2*step*step;
    float hR  = fmaf(K1, g0, K2);
    float t1  = ex2(2.f*K2);
    float t2  = t1*t1;
    float sc  = t2*t2;                 // 2^{8 K2}
    ull acc2[8];
    #pragma unroll
    for (int k=0;k<8;k++) acc2[k] = 0ull;
    const float2* abp = sab + half*256;
    for (int n=0;n<256;n++){
        float2 abv = abp[n];
        float QA  = fmaf(abv.y, g0, q0) + abv.x;
        float Ra  = fmaf(abv.y, step, hR);
        float eA  = ex2(QA);
        float rho = ex2(Ra);
        float eB  = eA*rho;
        float rA  = rho*rho*t1;
        float rB  = rA*t2;
        ull e2 = pk2(eA, eB);
        ull r2 = pk2(rA, rB);
        acc2[0] = add2(acc2[0], e2);
        #pragma unroll
        for (int k=1;k<8;k++){
            e2 = mul2(e2, r2);
            acc2[k] = add2(acc2[k], e2);
        }
    }
    // unpack raw partials, exchange via pmem (own half region = own sab bytes)
    float dens[16];
    #pragma unroll
    for (int k=0;k<8;k++) up2(dens[2*k], dens[2*k+1], acc2[k]);
    float* fb = (float*)pmem;                    // 1024 floats
    #pragma unroll
    for (int j=0;j<16;j++) fb[half*512 + lane*16 + j] = dens[j];
    PAIR_BAR(pid);
    {
        const float4* pf = (const float4*)&fb[(half^1)*512 + lane*16];
        #pragma unroll
        for (int k4=0;k4<4;k4++){
            float4 pv = pf[k4];
            dens[k4*4+0] += pv.x; dens[k4*4+1] += pv.y;
            dens[k4*4+2] += pv.z; dens[k4*4+3] += pv.w;
        }
    }
    // scale by ck = sc^{k(k-1)/2}
    {
        float ck = 1.f, pk = 1.f;
        #pragma unroll
        for (int k=0;k<8;k++){
            dens[2*k]   *= ck;
            dens[2*k+1] *= ck;
            ck *= pk;
            pk *= sc;
        }
    }
    int pbase = lane*16;
    #pragma unroll
    for (int j=0;j<16;j++) if (pbase + j >= GRID_PTS) dens[j] = 0.f;
    float cdfl[16];
    float run = 0.f;
    #pragma unroll
    for (int j=0;j<16;j++){ run += dens[j]; cdfl[j] = run; }
    float tot = run, xs = run;
    for (int o=1;o<32;o<<=1){ float t_=__shfl_up_sync(0xffffffffu,xs,o); if (lane>=o) xs+=t_; }
    float basev = xs - tot;
    #pragma unroll
    for (int j=0;j<16;j++) cdfl[j] += basev;
    float total = __shfl_sync(0xffffffffu, cdfl[15], 31);
    float invT  = 1.f/fmaxf(total, 1e-8f);
    #pragma unroll
    for (int j=0;j<16;j++){
        cdfl[j] *= invT;
        if (pbase + j >= GRID_PTS) cdfl[j] = 4e9f;   // sentinel -> wgt == 0
    }
    float gpv[16];
    #pragma unroll
    for (int j=0;j<16;j++) gpv[j] = fmaf((float)(pbase+j), step, mnA);
    // quantiles split: warp half handles q = half*10 .. half*10+9
    for (int qi=0; qi<10; qi+=2){
        int q = half*10 + qi;
        float qa = q*(1.f/19.f), qb = (q+1)*(1.f/19.f);
        float swa=0.f, swga=0.f, swb=0.f, swgb=0.f;
        #pragma unroll
        for (int j=0;j<16;j++){
            float da = fabsf(cdfl[j] - qa);
            float db = fabsf(cdfl[j] - qb);
            float wa = rcpf(1.f + ex2(144.269504f*da));
            float wb = rcpf(1.f + ex2(144.269504f*db));
            swa += wa; swga = fmaf(wa, gpv[j], swga);
            swb += wb; swgb = fmaf(wb, gpv[j], swgb);
        }
        #pragma unroll
        for (int o=16;o;o>>=1){
            swa += __shfl_xor_sync(0xffffffffu,swa,o);
            swga+= __shfl_xor_sync(0xffffffffu,swga,o);
            swb += __shfl_xor_sync(0xffffffffu,swb,o);
            swgb+= __shfl_xor_sync(0xffffffffu,swgb,o);
        }
        if (lane==0){
            g_kf[rg*2560 + d*NQ + q]   = swga/(swa + 1e-8f);
            g_kf[rg*2560 + d*NQ + q+1] = swgb/(swb + 1e-8f);
        }
    }
}

// ---------------- the single persistent kernel ----------------
__global__ void __launch_bounds__(NTHR, 1) k_mega(
    const float* __restrict__ x, const int* __restrict__ ei,
    const float* W0, const float* as0, const float* ad0, const float* b0,
    const float* W1, const float* as1, const float* ad1, const float* b1,
    const float* lpW0, const float* lpb0, const float* lpW1, const float* lpb1,
    const float* lpW2, const float* lpb2,
    const float* kW0, const float* kb0, const float* kW1, const float* kb1,
    const float* kW2, const float* kb2,
    const float* pw, const float* beta, const float* h0, float* out)
{
    __shared__ __align__(16) char smem[29184];   // 7 pairs x 4KB + sred + padding
    float* sred = (float*)(smem + 28672);        // 7 pairs x 8 floats
    int b = blockIdx.x, tid = threadIdx.x;
    int w = tid>>5, lane = tid&31;

    if (b < ABLK){
        // ---- Team A: edge fill + GAT chain ----
        {
            int e = b*NTHR + tid;
            int dd = ei[NEDGE+e];                     // e < 24576 < NEDGE
            int pos = atomicAdd(&g_cursor[dd], 1);
            if (pos < DEGCAP) g_adjB[dd*DEGCAP + pos] = ei[e];
            int e2i = e + ABLK*NTHR;
            if (e2i < NEDGE){
                int d2 = ei[NEDGE+e2i];
                int p2 = atomicAdd(&g_cursor[d2], 1);
                if (p2 < DEGCAP) g_adjB[d2*DEGCAP + p2] = ei[e2i];
            }
        }
        sync_n(1, ABLK);
        lin_phase(x, W0, as0, ad0, b, tid, smem);
        sync_n(1, ABLK);
        att_phase(b0, 0, b, tid, smem);
        sync_n(1, ABLK);
        lin_phase(g_cur1, W1, as1, ad1, b, tid, smem);
        sync_n(1, ABLK);
        att_phase(b1, 1, b, tid, smem);
    } else {
        // ---- Team B: transpose x + densq ro=0 ----
        int bb = b - ABLK;                            // 0..99
        if (bb < 64){
            float (*tile)[129] = (float(*)[129])smem;
            int n0 = bb*32;
            #pragma unroll
            for (int i=0;i<8;i++){
                int idx = tid + i*NTHR;
                int nn = idx>>7, d = idx&127;
                tile[nn][d] = x[(size_t)(n0+nn)*DIM + d];
            }
            __syncthreads();
            #pragma unroll
            for (int i=0;i<8;i++){
                int idx = tid + i*NTHR;
                int d = idx>>5, nn = idx&31;
                g_xT[(size_t)d*N_NODES + n0 + nn] = tile[nn][d];
            }
        }
        sync_n(2, BBLK);
        {
            int p = w>>1, half = w&1;
            int u = p*BBLK + bb;
            if (p < 6 && u < 512)
                densq_unit2(u>>7, u&127, pw, smem + p*4096, sred + p*8, half, lane, p);
        }
    }
    sync_n(0, NBLK);     // full join

    // ---- all blocks: densq ro=1,2 (1024 units, 2 warps each) ----
    {
        int p = w>>1, half = w&1;
        int u = p*NBLK + b;
        if (u < 1024)
            densq_unit2(4 + (u>>7), u&127, pw, smem + p*4096, sred + p*8, half, lane, p);
    }
    sync_n(0, NBLK);

    // ---- epilogue: cursor re-zero + projections + final ----
    {
        int idx = b*NTHR + tid;
        if (idx < N_NODES) g_cursor[idx] = 0;
    }
    if (b < NRG){
        int rg = b, g = rg&3, ro = rg>>2;
        const float* lpW = (ro==0)?lpW0:(ro==1)?lpW1:lpW2;
        const float* lpb = (ro==0)?lpb0:(ro==1)?lpb1:lpb2;
        const float* kW  = (ro==0)?kW0 :(ro==1)?kW1 :kW2;
        const float* kb  = (ro==0)?kb0 :(ro==1)?kb1 :kb2;
        float* r1  = (float*)smem;
        float* r2s = r1 + 256;
        int*   slast = (int*)(smem + 2048);
        int o = tid&31, seg = tid>>5;
        float kp = 0.f, hp = 0.f;
        if (tid < 256){
            const float* kf = &g_kf[rg*2560];
            for (int i=seg*320; i<seg*320+320; i++)
                kp = fmaf(kf[i], kW[i*32 + o], kp);
            const float* wp = &g_pool[rg*DIM];
            for (int dd=seg*16; dd<seg*16+16; dd++)
                hp = fmaf(wp[dd], lpW[dd*32 + o], hp);
            r1[tid] = kp; r2s[tid] = hp;
        }
        __syncthreads();
        if (tid < 32){
            float ks=0.f, hs=0.f;
            #pragma unroll
            for (int s=0;s<8;s++){ ks += r1[tid + s*32]; hs += r2s[tid + s*32]; }
            float val = (ks + kb[tid]) + (hs + lpb[tid]);
            atomicAdd(&g_acc[g*32 + tid], val*(1.f/3.f));
        }
        __threadfence();
        __syncthreads();
        if (tid == 0){
            int prev = atomicAdd(&g_done, 1);
            *slast = (prev == NRG-1);
        }
        __syncthreads();
        if (*slast && tid < 128){
            __threadfence();
            int gg = tid>>5, oo = tid&31;
            float vv = g_acc[gg*32 + oo]*beta[oo];
            #pragma unroll
            for (int ofs=16; ofs; ofs>>=1) vv += __shfl_xor_sync(0xffffffffu, vv, ofs);
            if (oo==0) out[gg] = vv + h0[0];
            g_acc[tid] = 0.f;           // reset for next replay
            if (tid == 0) g_done = 0;
        }
    }
}

extern "C" void kernel_launch(void* const* d_in, const int* in_sizes, int n_in,
                              void* d_out, int out_size){
    const float* x   = (const float*)d_in[0];
    const int*   ei  = (const int*)d_in[1];
    const float* W0  = (const float*)d_in[3];
    const float* as0 = (const float*)d_in[4];
    const float* ad0 = (const float*)d_in[5];
    const float* b0  = (const float*)d_in[6];
    const float* W1  = (const float*)d_in[7];
    const float* as1 = (const float*)d_in[8];
    const float* ad1 = (const float*)d_in[9];
    const float* b1  = (const float*)d_in[10];
    const float* lpW0=(const float*)d_in[11]; const float* lpb0=(const float*)d_in[12];
    const float* lpW1=(const float*)d_in[13]; const float* lpb1=(const float*)d_in[14];
    const float* lpW2=(const float*)d_in[15]; const float* lpb2=(const float*)d_in[16];
    const float* kW0 =(const float*)d_in[17]; const float* kb0 =(const float*)d_in[18];
    const float* kW1 =(const float*)d_in[19]; const float* kb1 =(const float*)d_in[20];
    const float* kW2 =(const float*)d_in[21]; const float* kb2 =(const float*)d_in[22];
    const float* poolw=(const float*)d_in[23];
    const float* beta =(const float*)d_in[24];
    const float* h0   =(const float*)d_in[25];
    float* out = (float*)d_out;

    k_mega<<<NBLK, NTHR>>>(x, ei, W0, as0, ad0, b0, W1, as1, ad1, b1,
                           lpW0, lpb0, lpW1, lpb1, lpW2, lpb2,
                           kW0, kb0, kW1, kb1, kW2, kb2,
                           poolw, beta, h0, out);
}

// round 12
// speedup vs baseline: 1.2388x; 1.2388x over previous
#include <cuda_runtime.h>

#define N_NODES 2048
#define NGR 512
#define NGRAPH 4
#define NEDGE 32768
#define DIM 128
#define HEADS 4
#define GRID_PTS 500
#define NQ 20
#define NRG 12
#define DEGCAP 64
#define NBLK 148
#define NTHR 512

typedef unsigned long long ull;

__device__ float g_xh[N_NODES*DIM];
__device__ float g_als[N_NODES*HEADS];
__device__ float g_ald[N_NODES*HEADS];
__device__ float g_cur1[N_NODES*DIM];
__device__ float g_xT [DIM*N_NODES];
__device__ float g_c1T[DIM*N_NODES];
__device__ float g_c2T[DIM*N_NODES];
__device__ int   g_cursor[N_NODES];
__device__ int   g_adjB[N_NODES*DEGCAP];
__device__ float g_pool[NRG*DIM];
__device__ float g_kf[NRG*DIM*NQ];
__device__ float g_acc[NGRAPH*32];
__device__ int   g_done;
__device__ unsigned g_barCnt;
__device__ volatile unsigned g_barGen;

__device__ __forceinline__ float ex2(float x){
    float y; asm("ex2.approx.ftz.f32 %0, %1;" : "=f"(y) : "f"(x)); return y;
}
__device__ __forceinline__ float rcpf(float x){
    float y; asm("rcp.approx.ftz.f32 %0, %1;" : "=f"(y) : "f"(x)); return y;
}
__device__ __forceinline__ ull pk2(float lo, float hi){
    ull o; asm("mov.b64 %0, {%1, %2};" : "=l"(o) : "f"(lo), "f"(hi)); return o;
}
__device__ __forceinline__ void up2(float& lo, float& hi, ull v){
    asm("mov.b64 {%0, %1}, %2;" : "=f"(lo), "=f"(hi) : "l"(v));
}
__device__ __forceinline__ ull mul2(ull a, ull b){
    ull o; asm("mul.rn.f32x2 %0, %1, %2;" : "=l"(o) : "l"(a), "l"(b)); return o;
}
__device__ __forceinline__ ull add2(ull a, ull b){
    ull o; asm("add.rn.f32x2 %0, %1, %2;" : "=l"(o) : "l"(a), "l"(b)); return o;
}

__device__ __forceinline__ void grid_sync(){
    __syncthreads();
    if (threadIdx.x == 0){
        __threadfence();
        unsigned gen = g_barGen;
        if (atomicAdd(&g_barCnt, 1u) == (unsigned)(NBLK-1)){
            atomicExch(&g_barCnt, 0u);
            __threadfence();
            g_barGen = gen + 1u;
        } else {
            while (g_barGen == gen) __nanosleep(32);
        }
        __threadfence();
    }
    __syncthreads();
}

#define GROUP_BAR(gid) asm volatile("bar.sync %0, %1;" :: "r"((gid)+4), "r"(128) : "memory")

__device__ void lin_phase(const float* __restrict__ cur,
                          const float* __restrict__ W,
                          const float* __restrict__ as_,
                          const float* __restrict__ ad_,
                          int b, int tid, char* smem){
    int g = tid>>7, gt = tid&127;
    int tI = g*NBLK + b;
    bool act = (tI < N_NODES/8);
    float (*srow)[128] = (float(*)[128])(smem + g*4096);
    int n0 = tI*8;
    if (act){
        #pragma unroll
        for (int i=0;i<8;i++){
            int idx = gt + i*128;
            srow[idx>>7][idx&127] = cur[(size_t)n0*DIM + idx];
        }
    }
    GROUP_BAR(g);
    if (act){
        float acc[8] = {0,0,0,0,0,0,0,0};
        #pragma unroll 4
        for (int k4=0;k4<32;k4++){
            float w0 = W[(k4*4+0)*DIM + gt];
            float w1 = W[(k4*4+1)*DIM + gt];
            float w2 = W[(k4*4+2)*DIM + gt];
            float w3 = W[(k4*4+3)*DIM + gt];
            #pragma unroll
            for (int j=0;j<8;j++){
                float4 sv = *(const float4*)&srow[j][k4*4];
                acc[j] = fmaf(sv.x, w0, acc[j]);
                acc[j] = fmaf(sv.y, w1, acc[j]);
                acc[j] = fmaf(sv.z, w2, acc[j]);
                acc[j] = fmaf(sv.w, w3, acc[j]);
            }
        }
        int hw = gt>>5;
        float a_s = as_[gt], a_d = ad_[gt];
        #pragma unroll
        for (int j=0;j<8;j++){
            g_xh[(size_t)(n0+j)*DIM + gt] = acc[j];
            float ps = acc[j]*a_s, pd = acc[j]*a_d;
            #pragma unroll
            for (int o=16;o;o>>=1){
                ps += __shfl_xor_sync(0xffffffffu, ps, o);
                pd += __shfl_xor_sync(0xffffffffu, pd, o);
            }
            if ((gt&31)==0){
                g_als[(n0+j)*HEADS + hw] = ps;
                g_ald[(n0+j)*HEADS + hw] = pd;
            }
        }
    }
}

// ---- attention: ONE WARP PER NODE (R10 proven version) ----
__device__ void att_phase(const float* __restrict__ bias, int layer,
                          int b, int tid, char* smem){
    int w = tid>>5, lane = tid&31;
    int n = w*NBLK + b;
    if (n < N_NODES){
        float* outT = layer ? g_c2T : g_c1T;
        char* base = smem + w*1376;
        int*   sadj = (int*)base;            // 68 ints
        float* sal  = (float*)(base + 272);  // [4][68] floats
        int deg = g_cursor[n]; if (deg > DEGCAP) deg = DEGCAP;
        int cnt = deg + 1;
        for (int i=lane; i<cnt; i+=32)
            sadj[i] = (i < deg) ? g_adjB[n*DEGCAP + i] : n;
        __syncwarp();
        int h = lane & 3, sub = lane >> 2;
        float aldn = g_ald[n*HEADS + h];
        int nch = (cnt + 7) >> 3;
        float mx = -1e30f;
        for (int c=0;c<nch;c++){
            int i = c*8 + sub;
            if (i < cnt){
                float z = g_als[sadj[i]*HEADS + h] + aldn;
                z = (z>0.f) ? z : 0.2f*z;
                sal[h*68 + i] = z;
                mx = fmaxf(mx, z);
            }
        }
        mx = fmaxf(mx, __shfl_xor_sync(0xffffffffu, mx, 4));
        mx = fmaxf(mx, __shfl_xor_sync(0xffffffffu, mx, 8));
        mx = fmaxf(mx, __shfl_xor_sync(0xffffffffu, mx, 16));
        float sum = 0.f;
        for (int c=0;c<nch;c++){
            int i = c*8 + sub;
            if (i < cnt){
                float e = __expf(sal[h*68+i] - mx);
                sal[h*68+i] = e;
                sum += e;
            }
        }
        sum += __shfl_xor_sync(0xffffffffu, sum, 4);
        sum += __shfl_xor_sync(0xffffffffu, sum, 8);
        sum += __shfl_xor_sync(0xffffffffu, sum, 16);
        float inv = 1.f/(sum + 1e-16f);
        float invA = __shfl_sync(0xffffffffu, inv, lane>>3);
        __syncwarp();
        const float* salh = sal + (lane>>3)*68;
        float ax=0.f, ay=0.f, az=0.f, aw=0.f;
        int i=0;
        for (; i+4<=cnt; i+=4){
            float a0=salh[i], a1=salh[i+1], a2=salh[i+2], a3=salh[i+3];
            float4 x0 = *(const float4*)&g_xh[(size_t)sadj[i  ]*DIM + lane*4];
            float4 x1 = *(const float4*)&g_xh[(size_t)sadj[i+1]*DIM + lane*4];
            float4 x2 = *(const float4*)&g_xh[(size_t)sadj[i+2]*DIM + lane*4];
            float4 x3 = *(const float4*)&g_xh[(size_t)sadj[i+3]*DIM + lane*4];
            ax=fmaf(a0,x0.x,ax); ay=fmaf(a0,x0.y,ay); az=fmaf(a0,x0.z,az); aw=fmaf(a0,x0.w,aw);
            ax=fmaf(a1,x1.x,ax); ay=fmaf(a1,x1.y,ay); az=fmaf(a1,x1.z,az); aw=fmaf(a1,x1.w,aw);
            ax=fmaf(a2,x2.x,ax); ay=fmaf(a2,x2.y,ay); az=fmaf(a2,x2.z,az); aw=fmaf(a2,x2.w,aw);
            ax=fmaf(a3,x3.x,ax); ay=fmaf(a3,x3.y,ay); az=fmaf(a3,x3.z,az); aw=fmaf(a3,x3.w,aw);
        }
        for (; i<cnt; i++){
            float a0 = salh[i];
            float4 x0 = *(const float4*)&g_xh[(size_t)sadj[i]*DIM + lane*4];
            ax=fmaf(a0,x0.x,ax); ay=fmaf(a0,x0.y,ay); az=fmaf(a0,x0.z,az); aw=fmaf(a0,x0.w,aw);
        }
        float4 bi = *(const float4*)&bias[lane*4];
        ax = fmaf(ax, invA, bi.x); ay = fmaf(ay, invA, bi.y);
        az = fmaf(az, invA, bi.z); aw = fmaf(aw, invA, bi.w);
        if (layer==0){
            ax=fmaxf(ax,0.f); ay=fmaxf(ay,0.f); az=fmaxf(az,0.f); aw=fmaxf(aw,0.f);
            *(float4*)&g_cur1[(size_t)n*DIM + lane*4] = make_float4(ax,ay,az,aw);
        }
        size_t cb = (size_t)(lane*4)*N_NODES + n;
        outT[cb]             = ax;
        outT[cb +   N_NODES] = ay;
        outT[cb + 2*N_NODES] = az;
        outT[cb + 3*N_NODES] = aw;
    }
}

// ---- densq: paired-node 16-step chain (18.5 fma-slots/node) ----
__device__ void densq_phase(const float* __restrict__ pw, int b, int w, int lane, char* smem){
    int u = w*NBLK + b;
    if (u >= NRG*DIM) return;
    int rg = u >> 7, d = u & 127;
    int ro = rg >> 2, g = rg & 3;
    const float* baseT = (ro==0) ? g_xT : (ro==1) ? g_c1T : g_c2T;
    float2* sab = (float2*)(smem + w*4096);
    const float* row = baseT + (size_t)d*N_NODES + g*NGR;

    float v[16];
    float mn=1e30f, mx=-1e30f, s1=0.f, s2=0.f;
    #pragma unroll
    for (int i=0;i<16;i++){
        float x = row[i*32 + lane];
        v[i] = x;
        mn = fminf(mn,x); mx = fmaxf(mx,x);
        s1 += x; s2 = fmaf(x,x,s2);
    }
    #pragma unroll
    for (int o=16;o;o>>=1){
        mn = fminf(mn, __shfl_xor_sync(0xffffffffu,mn,o));
        mx = fmaxf(mx, __shfl_xor_sync(0xffffffffu,mx,o));
        s1 += __shfl_xor_sync(0xffffffffu,s1,o);
        s2 += __shfl_xor_sync(0xffffffffu,s2,o);
    }
    float mean = s1*(1.f/512.f);
    float var  = fmaxf(s2*(1.f/512.f) - mean*mean, 0.f);
    float stdv = sqrtf(var) + 3.3333333e-9f;
    float h    = 0.30440506f*stdv;                   // 1.06*512^-0.2
    float c2   = -0.72134752f/(h*h);                 // -0.5*log2(e)/h^2
    float mnA = mn - 1e-6f, mxA = mx + 1e-6f;
    float step = (mxA - mnA)*(1.f/499.f);
    float mid  = 0.5f*(mnA + mxA);
    if (lane==0) g_pool[rg*DIM + d] = pw[0]*mean + pw[1]*mx;

    #pragma unroll
    for (int i=0;i<16;i++){
        float xc = v[i] - mid;
        sab[i*32 + lane] = make_float2(c2*xc*xc, -2.f*c2*xc);
    }
    __syncwarp();

    float mnc = mnA - mid;
    float g0  = fmaf((float)(lane*16), step, mnc);
    float q0  = c2*g0*g0;
    float K1  = 2.f*c2*step, K2 = c2*step*step;
    float hR  = fmaf(K1, g0, K2);
    float t1  = ex2(2.f*K2);       // curvature factor, applied at epilogue
    ull acc2[16];
    #pragma unroll
    for (int k=0;k<16;k++) acc2[k] = 0ull;
    // two nodes per iteration packed in f32x2 lanes; 16-step step-1 chain:
    // e_k (unscaled) = e0 * r0^k ; true e_k = unscaled * t1^{k(k-1)/2}
    for (int n=0;n<256;n++){
        float2 A = sab[n];
        float2 B = sab[n+256];
        float QA = fmaf(A.y, g0, q0) + A.x;
        float QB = fmaf(B.y, g0, q0) + B.x;
        float Ra = fmaf(A.y, step, hR);
        float Rb = fmaf(B.y, step, hR);
        ull e2 = pk2(ex2(QA), ex2(QB));
        ull r2 = pk2(ex2(Ra), ex2(Rb));
        acc2[0] = add2(acc2[0], e2);
        #pragma unroll
        for (int k=1;k<16;k++){
            e2 = mul2(e2, r2);
            acc2[k] = add2(acc2[k], e2);
        }
    }
    float dens[16];
    {
        float ck = 1.f, pk = 1.f;      // ck = t1^{k(k-1)/2}, pk = t1^k
        #pragma unroll
        for (int k=0;k<16;k++){
            float lo, hi; up2(lo, hi, acc2[k]);
            dens[k] = (lo + hi)*ck;
            ck *= pk;
            pk *= t1;
        }
    }
    int pbase = lane*16;
    #pragma unroll
    for (int j=0;j<16;j++) if (pbase + j >= GRID_PTS) dens[j] = 0.f;
    float cdfl[16];
    float run = 0.f;
    #pragma unroll
    for (int j=0;j<16;j++){ run += dens[j]; cdfl[j] = run; }
    float tot = run, xs = run;
    for (int o=1;o<32;o<<=1){ float t_=__shfl_up_sync(0xffffffffu,xs,o); if (lane>=o) xs+=t_; }
    float basev = xs - tot;
    #pragma unroll
    for (int j=0;j<16;j++) cdfl[j] += basev;
    float total = __shfl_sync(0xffffffffu, cdfl[15], 31);
    float invT  = 1.f/fmaxf(total, 1e-8f);
    #pragma unroll
    for (int j=0;j<16;j++){
        cdfl[j] *= invT;
        if (pbase + j >= GRID_PTS) cdfl[j] = 4e9f;   // sentinel -> wgt == 0
    }
    float gpv[16];
    #pragma unroll
    for (int j=0;j<16;j++) gpv[j] = fmaf((float)(pbase+j), step, mnA);
    for (int q2=0; q2<NQ; q2+=2){
        float qa = q2*(1.f/19.f), qb = (q2+1)*(1.f/19.f);
        float swa=0.f, swga=0.f, swb=0.f, swgb=0.f;
        #pragma unroll
        for (int j=0;j<16;j++){
            float da = fabsf(cdfl[j] - qa);
            float db = fabsf(cdfl[j] - qb);
            float wa = rcpf(1.f + ex2(144.269504f*da));
            float wb = rcpf(1.f + ex2(144.269504f*db));
            swa += wa; swga = fmaf(wa, gpv[j], swga);
            swb += wb; swgb = fmaf(wb, gpv[j], swgb);
        }
        #pragma unroll
        for (int o=16;o;o>>=1){
            swa += __shfl_xor_sync(0xffffffffu,swa,o);
            swga+= __shfl_xor_sync(0xffffffffu,swga,o);
            swb += __shfl_xor_sync(0xffffffffu,swb,o);
            swgb+= __shfl_xor_sync(0xffffffffu,swgb,o);
        }
        if (lane==0){
            g_kf[rg*2560 + d*NQ + q2]   = swga/(swa + 1e-8f);
            g_kf[rg*2560 + d*NQ + q2+1] = swgb/(swb + 1e-8f);
        }
    }
}

__global__ void __launch_bounds__(NTHR, 1) k_mega(
    const float* __restrict__ x, const int* __restrict__ ei,
    const float* W0, const float* as0, const float* ad0, const float* b0,
    const float* W1, const float* as1, const float* ad1, const float* b1,
    const float* lpW0, const float* lpb0, const float* lpW1, const float* lpb1,
    const float* lpW2, const float* lpb2,
    const float* kW0, const float* kb0, const float* kW1, const float* kb1,
    const float* kW2, const float* kb2,
    const float* pw, const float* beta, const float* h0, float* out)
{
    __shared__ __align__(16) char smem[45056];
    int b = blockIdx.x, tid = threadIdx.x;
    int w = tid>>5, lane = tid&31;

    if (b == 0){
        if (tid < NGRAPH*32) g_acc[tid] = 0.f;
        if (tid == NGRAPH*32) g_done = 0;
    }
    {
        int e = b*NTHR + tid;
        if (e < NEDGE){
            int d = ei[NEDGE+e];
            int pos = atomicAdd(&g_cursor[d], 1);
            if (pos < DEGCAP) g_adjB[d*DEGCAP + pos] = ei[e];
        }
    }
    {
        float (*tile)[129] = (float(*)[129])smem;
        bool doT = (b < 64);
        int n0 = b*32;
        #pragma unroll
        for (int i=0;i<8;i++){
            int idx = tid + i*NTHR;
            int nn = idx>>7, d = idx&127;
            if (doT) tile[nn][d] = x[(size_t)(n0+nn)*DIM + d];
        }
        __syncthreads();
        #pragma unroll
        for (int i=0;i<8;i++){
            int idx = tid + i*NTHR;
            int d = idx>>5, nn = idx&31;
            if (doT) g_xT[(size_t)d*N_NODES + n0 + nn] = tile[nn][d];
        }
        __syncthreads();
    }
    lin_phase(x, W0, as0, ad0, b, tid, smem);
    grid_sync();

    att_phase(b0, 0, b, tid, smem);
    grid_sync();

    lin_phase(g_cur1, W1, as1, ad1, b, tid, smem);
    grid_sync();

    att_phase(b1, 1, b, tid, smem);
    grid_sync();

    densq_phase(pw, b, w, lane, smem);
    grid_sync();

    {
        int idx = b*NTHR + tid;
        if (idx < N_NODES) g_cursor[idx] = 0;
    }
    if (b < NRG){
        int rg = b, g = rg&3, ro = rg>>2;
        const float* lpW = (ro==0)?lpW0:(ro==1)?lpW1:lpW2;
        const float* lpb = (ro==0)?lpb0:(ro==1)?lpb1:lpb2;
        const float* kW  = (ro==0)?kW0 :(ro==1)?kW1 :kW2;
        const float* kb  = (ro==0)?kb0 :(ro==1)?kb1 :kb2;
        float* r1  = (float*)smem;
        float* r2s = r1 + 256;
        int*   slast = (int*)(smem + 2048);
        int o = tid&31, seg = tid>>5;
        float kp = 0.f, hp = 0.f;
        if (tid < 256){
            const float* kf = &g_kf[rg*2560];
            for (int i=seg*320; i<seg*320+320; i++)
                kp = fmaf(kf[i], kW[i*32 + o], kp);
            const float* wp = &g_pool[rg*DIM];
            for (int dd=seg*16; dd<seg*16+16; dd++)
                hp = fmaf(wp[dd], lpW[dd*32 + o], hp);
            r1[tid] = kp; r2s[tid] = hp;
        }
        __syncthreads();
        if (tid < 32){
            float ks=0.f, hs=0.f;
            #pragma unroll
            for (int s=0;s<8;s++){ ks += r1[tid + s*32]; hs += r2s[tid + s*32]; }
            float val = (ks + kb[tid]) + (hs + lpb[tid]);
            atomicAdd(&g_acc[g*32 + tid], val*(1.f/3.f));
        }
        __threadfence();
        __syncthreads();
        if (tid == 0){
            int prev = atomicAdd(&g_done, 1);
            *slast = (prev == NRG-1);
        }
        __syncthreads();
        if (*slast && tid < 128){
            __threadfence();
            int gg = tid>>5, oo = tid&31;
            float vv = g_acc[gg*32 + oo]*beta[oo];
            #pragma unroll
            for (int ofs=16; ofs; ofs>>=1) vv += __shfl_xor_sync(0xffffffffu, vv, ofs);
            if (oo==0) out[gg] = vv + h0[0];
        }
    }
}

extern "C" void kernel_launch(void* const* d_in, const int* in_sizes, int n_in,
                              void* d_out, int out_size){
    const float* x   = (const float*)d_in[0];
    const int*   ei  = (const int*)d_in[1];
    const float* W0  = (const float*)d_in[3];
    const float* as0 = (const float*)d_in[4];
    const float* ad0 = (const float*)d_in[5];
    const float* b0  = (const float*)d_in[6];
    const float* W1  = (const float*)d_in[7];
    const float* as1 = (const float*)d_in[8];
    const float* ad1 = (const float*)d_in[9];
    const float* b1  = (const float*)d_in[10];
    const float* lpW0=(const float*)d_in[11]; const float* lpb0=(const float*)d_in[12];
    const float* lpW1=(const float*)d_in[13]; const float* lpb1=(const float*)d_in[14];
    const float* lpW2=(const float*)d_in[15]; const float* lpb2=(const float*)d_in[16];
    const float* kW0 =(const float*)d_in[17]; const float* kb0 =(const float*)d_in[18];
    const float* kW1 =(const float*)d_in[19]; const float* kb1 =(const float*)d_in[20];
    const float* kW2 =(const float*)d_in[21]; const float* kb2 =(const float*)d_in[22];
    const float* poolw=(const float*)d_in[23];
    const float* beta =(const float*)d_in[24];
    const float* h0   =(const float*)d_in[25];
    float* out = (float*)d_out;

    k_mega<<<NBLK, NTHR>>>(x, ei, W0, as0, ad0, b0, W1, as1, ad1, b1,
                           lpW0, lpb0, lpW1, lpb1, lpW2, lpb2,
                           kW0, kb0, kW1, kb1, kW2, kb2,
                           poolw, beta, h0, out);
}